// round 1
// baseline (speedup 1.0000x reference)
#include <cuda_runtime.h>

#define BB 4
#define CC 256
#define OO 256
#define HH 192
#define WW 192
#define HWP (HH*WW)          // 36864
#define KSQ 9

// Scratch (allocation-free: __device__ globals)
__device__ float g_xn[BB*HWP*CC];   // x transposed to NHWC (151 MB)
__device__ float g_sx[BB*HWP];
__device__ float g_sy[BB*HWP];
__device__ float g_wt[KSQ*CC*OO];   // weight as [tap][c][o]

// ---- packed fp32 helpers (fma.rn.f32x2: 2x FFMA throughput on sm_103a) ----
__device__ __forceinline__ void fma2(unsigned long long& d, unsigned long long a, unsigned long long b) {
    asm("fma.rn.f32x2 %0, %1, %2, %3;" : "=l"(d) : "l"(a), "l"(b), "l"(d));
}
__device__ __forceinline__ unsigned long long pk(float lo, float hi) {
    unsigned long long r;
    asm("mov.b64 %0, {%1, %2};" : "=l"(r) : "f"(lo), "f"(hi));
    return r;
}
__device__ __forceinline__ void upk(float& lo, float& hi, unsigned long long v) {
    asm("mov.b64 {%0, %1}, %2;" : "=f"(lo), "=f"(hi) : "l"(v));
}

// ============ K1: NCHW -> NHWC transpose ============
__global__ void k_transpose(const float* __restrict__ x) {
    __shared__ float tile[32][33];
    int hw0 = blockIdx.x * 32;
    int c0  = blockIdx.y * 32;
    int b   = blockIdx.z;
    int tx = threadIdx.x, ty = threadIdx.y;
#pragma unroll
    for (int i = 0; i < 4; ++i) {
        int c = c0 + ty + i*8;
        tile[ty + i*8][tx] = x[(b*CC + c)*HWP + hw0 + tx];
    }
    __syncthreads();
#pragma unroll
    for (int i = 0; i < 4; ++i) {
        int hw = hw0 + ty + i*8;
        g_xn[(b*HWP + hw)*CC + c0 + tx] = tile[tx][ty + i*8];
    }
}

// ============ K2: scale-predictor conv (3x3, zero pad) -> sx, sy ============
__global__ void k_spconv(const float* __restrict__ x, const float* __restrict__ spw,
                         const float* __restrict__ spb) {
    __shared__ float ws[2*CC*9];       // 18 KB
    __shared__ float patch[10][36];
    int tx = threadIdx.x, ty = threadIdx.y;
    int tid = ty*32 + tx;
    for (int i = tid; i < 2*CC*9; i += 256) ws[i] = spw[i];
    int x0 = blockIdx.x*32, y0 = blockIdx.y*8, b = blockIdx.z;
    float a0 = spb[0], a1 = spb[1];
    for (int c = 0; c < CC; ++c) {
        __syncthreads();
        for (int t = tid; t < 340; t += 256) {
            int r = t / 34, cc = t - r*34;
            int gy = y0 + r - 1, gx = x0 + cc - 1;
            float v = 0.f;
            if (gy >= 0 && gy < HH && gx >= 0 && gx < WW)
                v = x[((b*CC + c)*HH + gy)*WW + gx];
            patch[r][cc] = v;
        }
        __syncthreads();
        const float* w0 = &ws[c*9];
        const float* w1 = &ws[(CC + c)*9];
#pragma unroll
        for (int dy = 0; dy < 3; ++dy)
#pragma unroll
            for (int dx = 0; dx < 3; ++dx) {
                float v = patch[ty+dy][tx+dx];
                a0 = fmaf(v, w0[dy*3+dx], a0);
                a1 = fmaf(v, w1[dy*3+dx], a1);
            }
    }
    int p = (b*HH + y0+ty)*WW + x0+tx;
    g_sx[p] = expf(fminf(fmaxf(a0, -2.f), 2.f));
    g_sy[p] = expf(fminf(fmaxf(a1, -2.f), 2.f));
}

// ============ K3: weight (O,C,3,3) -> wt[t][c][o] ============
__global__ void k_wtrans(const float* __restrict__ w) {
    int idx = blockIdx.x*256 + threadIdx.x;   // = (t*CC + c)*OO + o
    int o  = idx & 255;
    int tc = idx >> 8;
    int t  = tc / CC;
    int c  = tc - t*CC;
    g_wt[idx] = w[(o*CC + c)*9 + t];
}

// ============ K4: main implicit GEMM with bilinear-gathered A ============
// M tile = 64 pixels, N = 256 (all outputs), K = 9 taps * 256 ch, KC = 32.
__global__ __launch_bounds__(256, 2)
void k_main(const float* __restrict__ bias, float* __restrict__ out) {
    __shared__ float As[32][65];       // pad=1 -> conflict-free gather STS
    __shared__ float Bs[32*256];
    __shared__ float s_w00[64], s_w01[64], s_w10[64], s_w11[64];
    __shared__ int   s_o00[64], s_o01[64], s_o10[64], s_o11[64];
    __shared__ float s_gxb[64], s_gyb[64], s_sxv[64], s_syv[64];

    const int tid = threadIdx.x;
    const int m0  = blockIdx.x * 64;
    const int b   = m0 / HWP;          // tile never crosses batch (64 | HW)
    const int p0  = m0 - b*HWP;
    const int pb  = b * HWP;

    if (tid < 64) {
        int p = m0 + tid;
        int r = p - pb;
        int y = r / WW;
        int xx = r - y*WW;
        s_gxb[tid] = (float)xx;
        s_gyb[tid] = (float)y;
        s_sxv[tid] = g_sx[p];
        s_syv[tid] = g_sy[p];
    }

    const int tx = tid & 7;            // m-group (8 x 8 pixels)
    const int ty = tid >> 3;           // n-group (32 x 8 outputs)
    const int mb = tx * 8;
    const int n0 = ty * 8;

    unsigned long long acc[8][4];
#pragma unroll
    for (int i = 0; i < 8; ++i)
#pragma unroll
        for (int j = 0; j < 4; ++j) acc[i][j] = 0ull;

    for (int t = 0; t < 9; ++t) {
        // per-tap bilinear coords/weights (channel-invariant), by threads 0..63.
        // Safe without an extra barrier: all reads of the previous tap's coord
        // arrays completed before the barrier preceding the last FMA phase.
        if (tid < 64) {
            float cx = (float)(t % 3 - 1);
            float cy = (float)(t / 3 - 1);
            float gx = fminf(fmaxf(s_gxb[tid] + cx*s_sxv[tid], 0.f), (float)(WW-1));
            float gy = fminf(fmaxf(s_gyb[tid] + cy*s_syv[tid], 0.f), (float)(HH-1));
            float x0f = floorf(gx), y0f = floorf(gy);
            float wx = gx - x0f,   wy = gy - y0f;
            int ix0 = (int)x0f, iy0 = (int)y0f;
            int ix1 = min(ix0+1, WW-1), iy1 = min(iy0+1, HH-1);
            int r0 = pb + iy0*WW, r1 = pb + iy1*WW;
            s_o00[tid] = (r0 + ix0) * CC;
            s_o01[tid] = (r0 + ix1) * CC;
            s_o10[tid] = (r1 + ix0) * CC;
            s_o11[tid] = (r1 + ix1) * CC;
            s_w00[tid] = (1.f-wx)*(1.f-wy);
            s_w01[tid] = wx*(1.f-wy);
            s_w10[tid] = (1.f-wx)*wy;
            s_w11[tid] = wx*wy;
        }
        const float* wtt = g_wt + t * (CC*OO);

        for (int kc = 0; kc < 8; ++kc) {
            __syncthreads();   // prev FMA done + coords visible
            // B tile: contiguous 32 KB copy
            const float4* src = (const float4*)(wtt + kc*32*OO);
            float4* dst = (float4*)Bs;
#pragma unroll
            for (int r = 0; r < 8; ++r) dst[tid + r*256] = src[tid + r*256];
            // A tile: 64 px * 32 ch, float4 gathers over channels (coalesced)
#pragma unroll
            for (int r = 0; r < 2; ++r) {
                int tsk = tid + r*256;
                int p = tsk >> 3;        // pixel
                int g = tsk & 7;         // channel group of 4
                int cbase = kc*32 + g*4;
                const float4 v00 = *(const float4*)(g_xn + s_o00[p] + cbase);
                const float4 v01 = *(const float4*)(g_xn + s_o01[p] + cbase);
                const float4 v10 = *(const float4*)(g_xn + s_o10[p] + cbase);
                const float4 v11 = *(const float4*)(g_xn + s_o11[p] + cbase);
                float w00 = s_w00[p], w01 = s_w01[p];
                float w10 = s_w10[p], w11 = s_w11[p];
                int kk = g*4;
                As[kk+0][p] = w00*v00.x + w01*v01.x + w10*v10.x + w11*v11.x;
                As[kk+1][p] = w00*v00.y + w01*v01.y + w10*v10.y + w11*v11.y;
                As[kk+2][p] = w00*v00.z + w01*v01.z + w10*v10.z + w11*v11.z;
                As[kk+3][p] = w00*v00.w + w01*v01.w + w10*v10.w + w11*v11.w;
            }
            __syncthreads();
            // GEMM micro-kernel: 8x8 frag, packed f32x2 FMAs
#pragma unroll
            for (int kk = 0; kk < 32; ++kk) {
                float a[8];
#pragma unroll
                for (int i = 0; i < 8; ++i) a[i] = As[kk][mb + i];
                const float4 b0 = *(const float4*)&Bs[kk*256 + n0];
                const float4 b1 = *(const float4*)&Bs[kk*256 + n0 + 4];
                unsigned long long bp0 = pk(b0.x, b0.y);
                unsigned long long bp1 = pk(b0.z, b0.w);
                unsigned long long bp2 = pk(b1.x, b1.y);
                unsigned long long bp3 = pk(b1.z, b1.w);
#pragma unroll
                for (int i = 0; i < 8; ++i) {
                    unsigned long long ap = pk(a[i], a[i]);
                    fma2(acc[i][0], ap, bp0);
                    fma2(acc[i][1], ap, bp1);
                    fma2(acc[i][2], ap, bp2);
                    fma2(acc[i][3], ap, bp3);
                }
            }
        }
    }

    // epilogue: unpack, add bias, coalesced float4 stores to NCHW
    float accf[8][8];
#pragma unroll
    for (int i = 0; i < 8; ++i)
#pragma unroll
        for (int j = 0; j < 4; ++j)
            upk(accf[i][2*j], accf[i][2*j+1], acc[i][j]);

#pragma unroll
    for (int j = 0; j < 8; ++j) {
        int o = n0 + j;
        float bv = bias[o];
        float* op = out + (b*OO + o)*HWP + p0 + mb;
        float4 lo = make_float4(accf[0][j]+bv, accf[1][j]+bv, accf[2][j]+bv, accf[3][j]+bv);
        float4 hi = make_float4(accf[4][j]+bv, accf[5][j]+bv, accf[6][j]+bv, accf[7][j]+bv);
        *(float4*)op     = lo;
        *(float4*)(op+4) = hi;
    }
}

extern "C" void kernel_launch(void* const* d_in, const int* in_sizes, int n_in,
                              void* d_out, int out_size) {
    const float* x    = (const float*)d_in[0];
    const float* w    = (const float*)d_in[1];
    const float* bias = (const float*)d_in[2];
    const float* spw  = (const float*)d_in[3];
    const float* spb  = (const float*)d_in[4];
    float* out = (float*)d_out;

    k_transpose<<<dim3(HWP/32, CC/32, BB), dim3(32, 8)>>>(x);
    k_spconv  <<<dim3(WW/32, HH/8, BB),  dim3(32, 8)>>>(x, spw, spb);
    k_wtrans  <<<(KSQ*CC*OO)/256, 256>>>(w);
    k_main    <<<(BB*HWP)/64, 256>>>(bias, out);
}

// round 3
// speedup vs baseline: 2.0981x; 2.0981x over previous
#include <cuda_runtime.h>
#include <cuda_bf16.h>
#include <cstdint>

#define BB 4
#define CC 256
#define OO 256
#define HH 192
#define WW 192
#define HWP (HH*WW)          // 36864
#define KK 2304              // 9 taps * 256 ch
#define MT 128               // pixels per CTA tile
#define KC 64                // k per chunk
#define NCHUNK (KK/KC)       // 36
#define SA 72                // padded row stride (bf16 elems): 144B, conflict-free

// ---- scratch (__device__ globals: allocation-free) ----
__device__ float g_xn[(size_t)BB*HWP*CC];     // NHWC x
__device__ float g_sx[BB*HWP];
__device__ float g_sy[BB*HWP];
__device__ __nv_bfloat16 g_wh[OO*KK];         // weight hi, [o][t*256+c]
__device__ __nv_bfloat16 g_wl[OO*KK];         // weight lo

// ================= helpers (plain sm_80+ PTX only) =================
__device__ __forceinline__ uint32_t s2u(const void* p) {
    uint32_t a;
    asm("{ .reg .u64 t; cvta.to.shared.u64 t, %1; cvt.u32.u64 %0, t; }" : "=r"(a) : "l"(p));
    return a;
}
// pack two fp32 -> bf16x2 (first arg -> low half)
__device__ __forceinline__ uint32_t bfpack(float lo, float hi) {
    uint32_t r;
    asm("cvt.rn.bf16x2.f32 %0, %1, %2;" : "=r"(r) : "f"(hi), "f"(lo));
    return r;
}
__device__ __forceinline__ void sts64(uint32_t a, uint32_t x, uint32_t y) {
    asm volatile("st.shared.v2.b32 [%0], {%1, %2};" :: "r"(a), "r"(x), "r"(y) : "memory");
}
__device__ __forceinline__ void sts128(uint32_t a, float4 v) {
    asm volatile("st.shared.v4.f32 [%0], {%1, %2, %3, %4};"
                 :: "r"(a), "f"(v.x), "f"(v.y), "f"(v.z), "f"(v.w) : "memory");
}
__device__ __forceinline__ void ldm4(uint32_t* r, uint32_t a) {
    asm volatile("ldmatrix.sync.aligned.m8n8.x4.shared.b16 {%0,%1,%2,%3}, [%4];"
                 : "=r"(r[0]), "=r"(r[1]), "=r"(r[2]), "=r"(r[3]) : "r"(a));
}
__device__ __forceinline__ void mma16816(float* d, const uint32_t* a, uint32_t b0, uint32_t b1) {
    asm volatile("mma.sync.aligned.m16n8k16.row.col.f32.bf16.bf16.f32 "
                 "{%0,%1,%2,%3}, {%4,%5,%6,%7}, {%8,%9}, {%0,%1,%2,%3};"
                 : "+f"(d[0]), "+f"(d[1]), "+f"(d[2]), "+f"(d[3])
                 : "r"(a[0]), "r"(a[1]), "r"(a[2]), "r"(a[3]), "r"(b0), "r"(b1));
}

// smem byte offsets inside k_main dynamic smem
#define OFF_AHI 0
#define OFF_ALO 18432
#define OFF_BHI 36864
#define OFF_BLO 73728
#define OFF_CRD 110592
#define SMEM_DYN (110592 + 4096 + 64)

// ============ K1: NCHW -> NHWC transpose ============
__global__ void k_transpose(const float* __restrict__ x) {
    __shared__ float tile[32][33];
    int hw0 = blockIdx.x * 32, c0 = blockIdx.y * 32, b = blockIdx.z;
    int tx = threadIdx.x, ty = threadIdx.y;
#pragma unroll
    for (int i = 0; i < 4; ++i)
        tile[ty + i*8][tx] = x[(b*CC + c0 + ty + i*8)*HWP + hw0 + tx];
    __syncthreads();
#pragma unroll
    for (int i = 0; i < 4; ++i)
        g_xn[((size_t)b*HWP + hw0 + ty + i*8)*CC + c0 + tx] = tile[tx][ty + i*8];
}

// ============ K2: weight split to bf16 hi/lo, [o][t*256+c] ============
__global__ void k_wsplit(const float* __restrict__ w) {
    int idx = blockIdx.x*256 + threadIdx.x;      // o*KK + t*256 + c
    int o = idx / KK, k = idx - o*KK;
    int t = k >> 8, c = k & 255;
    float v = w[(o*CC + c)*9 + t];
    __nv_bfloat16 h = __float2bfloat16(v);
    g_wh[idx] = h;
    g_wl[idx] = __float2bfloat16(v - __bfloat162float(h));
}

// ============ K3: scale-predictor conv on NHWC ============
__global__ __launch_bounds__(256)
void k_spconv(const float* __restrict__ spw, const float* __restrict__ spb) {
    __shared__ float ws[2*9*256];                // [ch][tap][c]
    int tid = threadIdx.x;
    for (int i = tid; i < 2*9*256; i += 256) {
        int ch = i / 2304, rem = i - ch*2304;
        int t = rem >> 8, c = rem & 255;
        ws[i] = spw[(ch*CC + c)*9 + t];
    }
    __syncthreads();
    int p = blockIdx.x*256 + tid;
    int b = p / HWP, r = p - b*HWP;
    int y = r / WW, x = r - y*WW;
    float a0 = spb[0], a1 = spb[1];
#pragma unroll
    for (int t = 0; t < 9; ++t) {
        int dy = t/3 - 1, dx = t%3 - 1;
        int yy = y + dy, xx = x + dx;
        if (yy < 0 || yy >= HH || xx < 0 || xx >= WW) continue;
        const float* xr = g_xn + ((size_t)b*HWP + yy*WW + xx)*CC;
        const float* w0 = ws + t*256;
        const float* w1 = ws + 2304 + t*256;
        for (int c4 = 0; c4 < 256; c4 += 4) {
            float4 xv = *(const float4*)(xr + c4);
            float4 wa = *(const float4*)(w0 + c4);
            float4 wb = *(const float4*)(w1 + c4);
            a0 += xv.x*wa.x + xv.y*wa.y + xv.z*wa.z + xv.w*wa.w;
            a1 += xv.x*wb.x + xv.y*wb.y + xv.z*wb.z + xv.w*wb.w;
        }
    }
    g_sx[p] = expf(fminf(fmaxf(a0, -2.f), 2.f));
    g_sy[p] = expf(fminf(fmaxf(a1, -2.f), 2.f));
}

// ============ K4: main — gather + bf16x3 HMMA implicit GEMM ============
// 512 threads = 16 warps (4M x 4N). CTA tile M=128 px, N=256 out.
__global__ void __launch_bounds__(512, 1)
k_main(const float* __restrict__ bias, float* __restrict__ out) {
    extern __shared__ char sm[];
    const uint32_t SMB = s2u(sm);
    const uint32_t AHI = SMB + OFF_AHI, ALO = SMB + OFF_ALO;
    const uint32_t BHI = SMB + OFF_BHI, BLO = SMB + OFF_BLO;
    int*   so00 = (int*)  (sm + OFF_CRD);
    int*   so01 = (int*)  (sm + OFF_CRD + 512);
    int*   so10 = (int*)  (sm + OFF_CRD + 1024);
    int*   so11 = (int*)  (sm + OFF_CRD + 1536);
    float* sw00 = (float*)(sm + OFF_CRD + 2048);
    float* sw01 = (float*)(sm + OFF_CRD + 2560);
    float* sw10 = (float*)(sm + OFF_CRD + 3072);
    float* sw11 = (float*)(sm + OFF_CRD + 3584);

    const int tid  = threadIdx.x;
    const int wid  = tid >> 5, lane = tid & 31;
    const int wm   = wid & 3;          // M group (32 rows)
    const int wn   = wid >> 2;         // N group (64 cols)
    const int m0 = blockIdx.x * MT;
    const int b  = m0 / HWP;
    const int pb = b * HWP;
    const int p0 = m0 - pb;

    // ldmatrix lane address offsets (bytes)
    const int lrow = lane & 7;
    const int a_row16 = lrow + ((lane >> 3) & 1) * 8;
    const int a_k8    = (lane >> 4) * 8;
    const uint32_t aoff0 = (uint32_t)((wm*32 + a_row16) * SA + a_k8) * 2;
    const uint32_t aoff1 = aoff0 + 16*SA*2;
    const int b_n  = (lane >> 4) * 8 + lrow;
    const int b_k8 = ((lane >> 3) & 1) * 8;
    const uint32_t boff = (uint32_t)((wn*64 + b_n) * SA + b_k8) * 2;

    float acc[2][8][4];
#pragma unroll
    for (int i = 0; i < 2; ++i)
#pragma unroll
        for (int j = 0; j < 8; ++j)
#pragma unroll
            for (int q = 0; q < 4; ++q) acc[i][j][q] = 0.f;

    for (int kc = 0; kc < NCHUNK; ++kc) {
        const int t = kc >> 2;
        const int cbase = (kc & 3) * 64;

        if ((kc & 3) == 0 && tid < MT) {   // new tap: bilinear coords (1 px/thread)
            int p = m0 + tid;
            int r = p - pb;
            int y = r / WW, xx = r - y*WW;
            float cx = (float)(t % 3 - 1), cy = (float)(t / 3 - 1);
            float gx = fminf(fmaxf((float)xx + cx*g_sx[p], 0.f), (float)(WW-1));
            float gy = fminf(fmaxf((float)y  + cy*g_sy[p], 0.f), (float)(HH-1));
            float x0f = floorf(gx), y0f = floorf(gy);
            float wx = gx - x0f, wy = gy - y0f;
            int ix0 = (int)x0f, iy0 = (int)y0f;
            int ix1 = min(ix0+1, WW-1), iy1 = min(iy0+1, HH-1);
            int r0 = pb + iy0*WW, r1 = pb + iy1*WW;
            so00[tid] = (r0 + ix0) * CC;
            so01[tid] = (r0 + ix1) * CC;
            so10[tid] = (r1 + ix0) * CC;
            so11[tid] = (r1 + ix1) * CC;
            sw00[tid] = (1.f-wx)*(1.f-wy);
            sw01[tid] = wx*(1.f-wy);
            sw10[tid] = (1.f-wx)*wy;
            sw11[tid] = wx*wy;
        }
        __syncthreads();   // coords visible + prev MMA done reading tiles

        // ---- A gather: 128 px x 64 k -> bf16 hi/lo padded tiles ----
#pragma unroll
        for (int it = 0; it < 4; ++it) {
            int tau = tid + it*512;
            int p = tau >> 4;          // 0..127
            int j = tau & 15;          // 4-channel group
            int cb = cbase + j*4;
            const float4 v00 = *(const float4*)(g_xn + (size_t)so00[p] + cb);
            const float4 v01 = *(const float4*)(g_xn + (size_t)so01[p] + cb);
            const float4 v10 = *(const float4*)(g_xn + (size_t)so10[p] + cb);
            const float4 v11 = *(const float4*)(g_xn + (size_t)so11[p] + cb);
            float w00 = sw00[p], w01 = sw01[p], w10 = sw10[p], w11 = sw11[p];
            float f0 = w00*v00.x + w01*v01.x + w10*v10.x + w11*v11.x;
            float f1 = w00*v00.y + w01*v01.y + w10*v10.y + w11*v11.y;
            float f2 = w00*v00.z + w01*v01.z + w10*v10.z + w11*v11.z;
            float f3 = w00*v00.w + w01*v01.w + w10*v10.w + w11*v11.w;
            uint32_t h0 = bfpack(f0, f1);
            uint32_t h1 = bfpack(f2, f3);
            float r0f = f0 - __uint_as_float(h0 << 16);
            float r1f = f1 - __uint_as_float(h0 & 0xffff0000u);
            float r2f = f2 - __uint_as_float(h1 << 16);
            float r3f = f3 - __uint_as_float(h1 & 0xffff0000u);
            uint32_t l0 = bfpack(r0f, r1f);
            uint32_t l1 = bfpack(r2f, r3f);
            uint32_t off = (uint32_t)(p*SA*2 + j*8);
            sts64(AHI + off, h0, h1);
            sts64(ALO + off, l0, l1);
        }
        // ---- B copy: hi/lo x 256 rows x 128B (padded rows) ----
#pragma unroll
        for (int it = 0; it < 8; ++it) {
            int tau = tid + it*512;
            int tl = tau >> 11;
            int r  = (tau >> 3) & 255;
            int u  = tau & 7;
            const __nv_bfloat16* src = (tl ? g_wl : g_wh) + (size_t)r*KK + kc*KC + u*8;
            float4 v = *(const float4*)src;
            uint32_t off = (uint32_t)(r*SA*2 + u*16);
            sts128((tl ? BLO : BHI) + off, v);
        }
        __syncthreads();

        // ---- MMA: 4 k16 steps x 3 terms ----
#pragma unroll
        for (int ks = 0; ks < 4; ++ks) {
            uint32_t ah0[4], ah1[4], al0[4], al1[4];
            ldm4(ah0, AHI + aoff0 + ks*32);
            ldm4(ah1, AHI + aoff1 + ks*32);
            ldm4(al0, ALO + aoff0 + ks*32);
            ldm4(al1, ALO + aoff1 + ks*32);
#pragma unroll
            for (int nt = 0; nt < 4; ++nt) {
                uint32_t bh[4], bl[4];
                ldm4(bh, BHI + boff + nt*(16*SA*2) + ks*32);
                ldm4(bl, BLO + boff + nt*(16*SA*2) + ks*32);
                int n0 = nt*2;
                mma16816(acc[0][n0],   ah0, bh[0], bh[1]);
                mma16816(acc[0][n0+1], ah0, bh[2], bh[3]);
                mma16816(acc[1][n0],   ah1, bh[0], bh[1]);
                mma16816(acc[1][n0+1], ah1, bh[2], bh[3]);
                mma16816(acc[0][n0],   ah0, bl[0], bl[1]);
                mma16816(acc[0][n0+1], ah0, bl[2], bl[3]);
                mma16816(acc[1][n0],   ah1, bl[0], bl[1]);
                mma16816(acc[1][n0+1], ah1, bl[2], bl[3]);
                mma16816(acc[0][n0],   al0, bh[0], bh[1]);
                mma16816(acc[0][n0+1], al0, bh[2], bh[3]);
                mma16816(acc[1][n0],   al1, bh[0], bh[1]);
                mma16816(acc[1][n0+1], al1, bh[2], bh[3]);
            }
        }
    }

    // ---- epilogue: stage through smem, coalesced float4 NCHW stores ----
    float* ep = (float*)sm;            // [128 o][132 px stride]
    const int qrow = lane >> 2;
    const int qcol = (lane & 3) * 2;
#pragma unroll 1
    for (int h = 0; h < 2; ++h) {
        __syncthreads();
        if ((wn >> 1) == h) {
            int obase = (wn & 1) * 64;
#pragma unroll
            for (int mt = 0; mt < 2; ++mt) {
#pragma unroll
                for (int nn = 0; nn < 8; ++nn) {
                    int ol = obase + nn*8 + qcol;
                    int pr = wm*32 + mt*16 + qrow;
                    ep[ol*132 + pr]           = acc[mt][nn][0];
                    ep[(ol+1)*132 + pr]       = acc[mt][nn][1];
                    ep[ol*132 + pr + 8]       = acc[mt][nn][2];
                    ep[(ol+1)*132 + pr + 8]   = acc[mt][nn][3];
                }
            }
        }
        __syncthreads();
#pragma unroll
        for (int i = 0; i < 8; ++i) {
            int idx = tid + i*512;
            int o = idx >> 5;
            int q = idx & 31;
            int ov = h*128 + o;
            float bv = __ldg(&bias[ov]);
            const float* er = ep + o*132 + q*4;
            float4 v = make_float4(er[0]+bv, er[1]+bv, er[2]+bv, er[3]+bv);
            *(float4*)(out + ((size_t)(b*OO + ov))*HWP + p0 + q*4) = v;
        }
    }
}

extern "C" void kernel_launch(void* const* d_in, const int* in_sizes, int n_in,
                              void* d_out, int out_size) {
    const float* x    = (const float*)d_in[0];
    const float* w    = (const float*)d_in[1];
    const float* bias = (const float*)d_in[2];
    const float* spw  = (const float*)d_in[3];
    const float* spb  = (const float*)d_in[4];
    float* out = (float*)d_out;

    cudaFuncSetAttribute(k_main, cudaFuncAttributeMaxDynamicSharedMemorySize, SMEM_DYN);

    k_transpose<<<dim3(HWP/32, CC/32, BB), dim3(32, 8)>>>(x);
    k_wsplit  <<<(OO*KK)/256, 256>>>(w);
    k_spconv  <<<(BB*HWP)/256, 256>>>(spw, spb);
    k_main    <<<(BB*HWP)/MT, 512, SMEM_DYN>>>(bias, out);
}

// round 4
// speedup vs baseline: 2.4210x; 1.1539x over previous
#include <cuda_runtime.h>
#include <cuda_bf16.h>
#include <cstdint>

#define BB 4
#define CC 256
#define OO 256
#define HH 192
#define WW 192
#define HWP (HH*WW)          // 36864
#define KK 2304              // 9 taps * 256 ch
#define MT 64                // pixels per CTA tile
#define KC 64                // k per chunk
#define NCHUNK (KK/KC)       // 36
#define SA 72                // A padded row stride (bf16 elems)

// ---- scratch (__device__ globals: allocation-free) ----
__device__ float g_xn[(size_t)BB*HWP*CC];     // NHWC x
__device__ float g_sx[BB*HWP];
__device__ float g_sy[BB*HWP];
__device__ __nv_bfloat16 g_wh[OO*KK];         // weight hi, [o][t*256+c]
__device__ __nv_bfloat16 g_wl[OO*KK];         // weight lo

// ================= helpers (plain sm_80+ PTX only) =================
__device__ __forceinline__ uint32_t s2u(const void* p) {
    uint32_t a;
    asm("{ .reg .u64 t; cvta.to.shared.u64 t, %1; cvt.u32.u64 %0, t; }" : "=r"(a) : "l"(p));
    return a;
}
__device__ __forceinline__ uint32_t bfpack(float lo, float hi) {
    uint32_t r;
    asm("cvt.rn.bf16x2.f32 %0, %1, %2;" : "=r"(r) : "f"(hi), "f"(lo));
    return r;
}
__device__ __forceinline__ void sts64(uint32_t a, uint32_t x, uint32_t y) {
    asm volatile("st.shared.v2.b32 [%0], {%1, %2};" :: "r"(a), "r"(x), "r"(y) : "memory");
}
__device__ __forceinline__ void ldm4(uint32_t* r, uint32_t a) {
    asm volatile("ldmatrix.sync.aligned.m8n8.x4.shared.b16 {%0,%1,%2,%3}, [%4];"
                 : "=r"(r[0]), "=r"(r[1]), "=r"(r[2]), "=r"(r[3]) : "r"(a));
}
__device__ __forceinline__ void mma16816(float* d, const uint32_t* a, uint32_t b0, uint32_t b1) {
    asm volatile("mma.sync.aligned.m16n8k16.row.col.f32.bf16.bf16.f32 "
                 "{%0,%1,%2,%3}, {%4,%5,%6,%7}, {%8,%9}, {%0,%1,%2,%3};"
                 : "+f"(d[0]), "+f"(d[1]), "+f"(d[2]), "+f"(d[3])
                 : "r"(a[0]), "r"(a[1]), "r"(a[2]), "r"(a[3]), "r"(b0), "r"(b1));
}
__device__ __forceinline__ void cpasync16(uint32_t dst, const void* src) {
    asm volatile("cp.async.cg.shared.global [%0], [%1], 16;"
                 :: "r"(dst), "l"(__cvta_generic_to_global(src)) : "memory");
}

// smem layout (bytes)
#define OFF_AHI 0
#define OFF_ALO 9216
#define OFF_CRD 18432        // 8 arrays x 64 x 4B = 2048
#define OFF_BHI 20480        // 256 x 128B swizzled
#define OFF_BLO 53248
#define SMEM_DYN 86080

// ============ K1: NCHW -> NHWC transpose ============
__global__ void k_transpose(const float* __restrict__ x) {
    __shared__ float tile[32][33];
    int hw0 = blockIdx.x * 32, c0 = blockIdx.y * 32, b = blockIdx.z;
    int tx = threadIdx.x, ty = threadIdx.y;
#pragma unroll
    for (int i = 0; i < 4; ++i)
        tile[ty + i*8][tx] = x[(b*CC + c0 + ty + i*8)*HWP + hw0 + tx];
    __syncthreads();
#pragma unroll
    for (int i = 0; i < 4; ++i)
        g_xn[((size_t)b*HWP + hw0 + ty + i*8)*CC + c0 + tx] = tile[tx][ty + i*8];
}

// ============ K2: weight split to bf16 hi/lo, [o][t*256+c] ============
__global__ void k_wsplit(const float* __restrict__ w) {
    int idx = blockIdx.x*256 + threadIdx.x;      // o*KK + t*256 + c
    int o = idx / KK, k = idx - o*KK;
    int t = k >> 8, c = k & 255;
    float v = w[(o*CC + c)*9 + t];
    __nv_bfloat16 h = __float2bfloat16(v);
    g_wh[idx] = h;
    g_wl[idx] = __float2bfloat16(v - __bfloat162float(h));
}

// ============ K3: scale-predictor conv on NHWC ============
__global__ __launch_bounds__(256)
void k_spconv(const float* __restrict__ spw, const float* __restrict__ spb) {
    __shared__ float ws[2*9*256];                // [ch][tap][c]
    int tid = threadIdx.x;
    for (int i = tid; i < 2*9*256; i += 256) {
        int ch = i / 2304, rem = i - ch*2304;
        int t = rem >> 8, c = rem & 255;
        ws[i] = spw[(ch*CC + c)*9 + t];
    }
    __syncthreads();
    int p = blockIdx.x*256 + tid;
    int b = p / HWP, r = p - b*HWP;
    int y = r / WW, x = r - y*WW;
    float a0 = spb[0], a1 = spb[1];
#pragma unroll
    for (int t = 0; t < 9; ++t) {
        int dy = t/3 - 1, dx = t%3 - 1;
        int yy = y + dy, xx = x + dx;
        if (yy < 0 || yy >= HH || xx < 0 || xx >= WW) continue;
        const float* xr = g_xn + ((size_t)b*HWP + yy*WW + xx)*CC;
        const float* w0 = ws + t*256;
        const float* w1 = ws + 2304 + t*256;
        for (int c4 = 0; c4 < 256; c4 += 4) {
            float4 xv = *(const float4*)(xr + c4);
            float4 wa = *(const float4*)(w0 + c4);
            float4 wb = *(const float4*)(w1 + c4);
            a0 += xv.x*wa.x + xv.y*wa.y + xv.z*wa.z + xv.w*wa.w;
            a1 += xv.x*wb.x + xv.y*wb.y + xv.z*wb.z + xv.w*wb.w;
        }
    }
    g_sx[p] = expf(fminf(fmaxf(a0, -2.f), 2.f));
    g_sy[p] = expf(fminf(fmaxf(a1, -2.f), 2.f));
}

// ============ K4: main — gather + bf16x3 HMMA, 2 CTAs/SM for overlap ============
// 256 threads = 8 warps (2M x 4N). CTA tile M=64 px, N=256 out.
__global__ void __launch_bounds__(256, 2)
k_main(const float* __restrict__ bias, float* __restrict__ out) {
    extern __shared__ char sm[];
    const uint32_t SMB = s2u(sm);
    const uint32_t AHI = SMB + OFF_AHI, ALO = SMB + OFF_ALO;
    const uint32_t BHI = SMB + OFF_BHI, BLO = SMB + OFF_BLO;
    int*   so00 = (int*)  (sm + OFF_CRD);
    int*   so01 = (int*)  (sm + OFF_CRD + 256);
    int*   so10 = (int*)  (sm + OFF_CRD + 512);
    int*   so11 = (int*)  (sm + OFF_CRD + 768);
    float* sw00 = (float*)(sm + OFF_CRD + 1024);
    float* sw01 = (float*)(sm + OFF_CRD + 1280);
    float* sw10 = (float*)(sm + OFF_CRD + 1536);
    float* sw11 = (float*)(sm + OFF_CRD + 1792);

    const int tid  = threadIdx.x;
    const int wid  = tid >> 5, lane = tid & 31;
    const int wm   = wid & 1;          // M group (32 rows)
    const int wn   = wid >> 1;         // N group (64 cols)
    const int m0 = blockIdx.x * MT;
    const int b  = m0 / HWP;
    const int pb = b * HWP;
    const int p0 = m0 - pb;

    // ldmatrix lane addressing
    const int lrow = lane & 7;
    const int a_row16 = lrow + ((lane >> 3) & 1) * 8;
    const int a_k8    = (lane >> 4) * 8;
    const uint32_t aoff0 = (uint32_t)((wm*32 + a_row16) * SA + a_k8) * 2;
    const uint32_t aoff1 = aoff0 + 16*SA*2;
    const int b_n   = (lane >> 4) * 8 + lrow;
    const int brow  = wn*64 + b_n;
    const uint32_t bbase = (uint32_t)brow * 128u;
    const uint32_t bxor  = ((uint32_t)brow & 7u) << 4;
    const uint32_t bkk   = ((lane >> 3) & 1) * 16;

    float acc[2][8][4];
#pragma unroll
    for (int i = 0; i < 2; ++i)
#pragma unroll
        for (int j = 0; j < 8; ++j)
#pragma unroll
            for (int q = 0; q < 4; ++q) acc[i][j][q] = 0.f;

    for (int kc = 0; kc < NCHUNK; ++kc) {
        const int t = kc >> 2;
        const int cbase = (kc & 3) * 64;

        __syncthreads();   // prev MMA done: A/B/coords smem free

        // ---- B tiles via cp.async into swizzled layout (overlaps A gather) ----
#pragma unroll
        for (int it = 0; it < 16; ++it) {
            int tau = tid + it*256;
            int tl = tau >> 11;
            int r  = (tau >> 3) & 255;
            int u  = tau & 7;
            const __nv_bfloat16* src = (tl ? g_wl : g_wh) + (size_t)r*KK + kc*KC + u*8;
            uint32_t off = (uint32_t)(r*128 + u*16);
            uint32_t dst = (tl ? BLO : BHI) + (off ^ ((off >> 3) & 0x70u));
            cpasync16(dst, src);
        }
        asm volatile("cp.async.commit_group;" ::: "memory");

        if ((kc & 3) == 0) {     // new tap: bilinear coords (1 px/thread, tid<64)
            if (tid < MT) {
                int p = m0 + tid;
                int r = p - pb;
                int y = r / WW, xx = r - y*WW;
                float cx = (float)(t % 3 - 1), cy = (float)(t / 3 - 1);
                float gx = fminf(fmaxf((float)xx + cx*g_sx[p], 0.f), (float)(WW-1));
                float gy = fminf(fmaxf((float)y  + cy*g_sy[p], 0.f), (float)(HH-1));
                float x0f = floorf(gx), y0f = floorf(gy);
                float wx = gx - x0f, wy = gy - y0f;
                int ix0 = (int)x0f, iy0 = (int)y0f;
                int ix1 = min(ix0+1, WW-1), iy1 = min(iy0+1, HH-1);
                int r0 = pb + iy0*WW, r1 = pb + iy1*WW;
                so00[tid] = (r0 + ix0) * CC;
                so01[tid] = (r0 + ix1) * CC;
                so10[tid] = (r1 + ix0) * CC;
                so11[tid] = (r1 + ix1) * CC;
                sw00[tid] = (1.f-wx)*(1.f-wy);
                sw01[tid] = wx*(1.f-wy);
                sw10[tid] = (1.f-wx)*wy;
                sw11[tid] = wx*wy;
            }
            __syncthreads();
        }

        // ---- A gather: 64 px x 64 k -> bf16 hi/lo padded tiles ----
#pragma unroll
        for (int it = 0; it < 4; ++it) {
            int tau = tid + it*256;
            int p = tau >> 4;          // 0..63
            int j = tau & 15;          // 4-channel group
            int cb = cbase + j*4;
            const float4 v00 = *(const float4*)(g_xn + (size_t)so00[p] + cb);
            const float4 v01 = *(const float4*)(g_xn + (size_t)so01[p] + cb);
            const float4 v10 = *(const float4*)(g_xn + (size_t)so10[p] + cb);
            const float4 v11 = *(const float4*)(g_xn + (size_t)so11[p] + cb);
            float w00 = sw00[p], w01 = sw01[p], w10 = sw10[p], w11 = sw11[p];
            float f0 = w00*v00.x + w01*v01.x + w10*v10.x + w11*v11.x;
            float f1 = w00*v00.y + w01*v01.y + w10*v10.y + w11*v11.y;
            float f2 = w00*v00.z + w01*v01.z + w10*v10.z + w11*v11.z;
            float f3 = w00*v00.w + w01*v01.w + w10*v10.w + w11*v11.w;
            uint32_t h0 = bfpack(f0, f1);
            uint32_t h1 = bfpack(f2, f3);
            float r0f = f0 - __uint_as_float(h0 << 16);
            float r1f = f1 - __uint_as_float(h0 & 0xffff0000u);
            float r2f = f2 - __uint_as_float(h1 << 16);
            float r3f = f3 - __uint_as_float(h1 & 0xffff0000u);
            uint32_t l0 = bfpack(r0f, r1f);
            uint32_t l1 = bfpack(r2f, r3f);
            uint32_t off = (uint32_t)(p*SA*2 + j*8);
            sts64(AHI + off, h0, h1);
            sts64(ALO + off, l0, l1);
        }
        asm volatile("cp.async.wait_group 0;" ::: "memory");
        __syncthreads();

        // ---- MMA: 4 k16 steps x 3 terms ----
#pragma unroll
        for (int ks = 0; ks < 4; ++ks) {
            uint32_t ah0[4], ah1[4], al0[4], al1[4];
            ldm4(ah0, AHI + aoff0 + ks*32);
            ldm4(ah1, AHI + aoff1 + ks*32);
            ldm4(al0, ALO + aoff0 + ks*32);
            ldm4(al1, ALO + aoff1 + ks*32);
            uint32_t koff = ((uint32_t)(ks*32) + bkk) ^ bxor;
#pragma unroll
            for (int nt = 0; nt < 4; ++nt) {
                uint32_t bh[4], bl[4];
                ldm4(bh, BHI + bbase + nt*(16*128) + koff);
                ldm4(bl, BLO + bbase + nt*(16*128) + koff);
                int n0 = nt*2;
                mma16816(acc[0][n0],   ah0, bh[0], bh[1]);
                mma16816(acc[0][n0+1], ah0, bh[2], bh[3]);
                mma16816(acc[1][n0],   ah1, bh[0], bh[1]);
                mma16816(acc[1][n0+1], ah1, bh[2], bh[3]);
                mma16816(acc[0][n0],   ah0, bl[0], bl[1]);
                mma16816(acc[0][n0+1], ah0, bl[2], bl[3]);
                mma16816(acc[1][n0],   ah1, bl[0], bl[1]);
                mma16816(acc[1][n0+1], ah1, bl[2], bl[3]);
                mma16816(acc[0][n0],   al0, bh[0], bh[1]);
                mma16816(acc[0][n0+1], al0, bh[2], bh[3]);
                mma16816(acc[1][n0],   al1, bh[0], bh[1]);
                mma16816(acc[1][n0+1], al1, bh[2], bh[3]);
            }
        }
    }

    // ---- epilogue: stage all 256 o x 64 px through smem (stride 68) ----
    __syncthreads();
    float* ep = (float*)sm;
    const int qrow = lane >> 2;
    const int qcol = (lane & 3) * 2;
#pragma unroll
    for (int mt = 0; mt < 2; ++mt) {
#pragma unroll
        for (int nn = 0; nn < 8; ++nn) {
            int ol = wn*64 + nn*8 + qcol;
            int pr = wm*32 + mt*16 + qrow;
            ep[ol*68 + pr]         = acc[mt][nn][0];
            ep[(ol+1)*68 + pr]     = acc[mt][nn][1];
            ep[ol*68 + pr + 8]     = acc[mt][nn][2];
            ep[(ol+1)*68 + pr + 8] = acc[mt][nn][3];
        }
    }
    __syncthreads();
#pragma unroll
    for (int i = 0; i < 16; ++i) {
        int o = i*16 + (tid >> 4);
        int q = tid & 15;
        float bv = __ldg(&bias[o]);
        const float* er = ep + o*68 + q*4;
        float4 v = make_float4(er[0]+bv, er[1]+bv, er[2]+bv, er[3]+bv);
        *(float4*)(out + ((size_t)(b*OO + o))*HWP + p0 + q*4) = v;
    }
}

extern "C" void kernel_launch(void* const* d_in, const int* in_sizes, int n_in,
                              void* d_out, int out_size) {
    const float* x    = (const float*)d_in[0];
    const float* w    = (const float*)d_in[1];
    const float* bias = (const float*)d_in[2];
    const float* spw  = (const float*)d_in[3];
    const float* spb  = (const float*)d_in[4];
    float* out = (float*)d_out;

    cudaFuncSetAttribute(k_main, cudaFuncAttributeMaxDynamicSharedMemorySize, SMEM_DYN);

    k_transpose<<<dim3(HWP/32, CC/32, BB), dim3(32, 8)>>>(x);
    k_wsplit  <<<(OO*KK)/256, 256>>>(w);
    k_spconv  <<<(BB*HWP)/256, 256>>>(spw, spb);
    k_main    <<<(BB*HWP)/MT, 256, SMEM_DYN>>>(bias, out);
}

// round 5
// speedup vs baseline: 3.5415x; 1.4628x over previous
#include <cuda_runtime.h>
#include <cuda_fp16.h>
#include <cstdint>

#define BB 4
#define CC 256
#define OO 256
#define HH 192
#define WW 192
#define HWP (HH*WW)          // 36864
#define KK 2304              // 9 taps * 256 ch
#define MT 64                // pixels per CTA tile
#define KC 64                // k per chunk
#define NCHUNK (KK/KC)       // 36
#define SA 72                // A padded row stride (fp16 elems)

// ---- scratch (__device__ globals: allocation-free) ----
__device__ float g_xn[(size_t)BB*HWP*CC];     // NHWC x
__device__ float g_sx[BB*HWP];
__device__ float g_sy[BB*HWP];
__device__ __half g_wh[OO*KK];                // weight hi fp16, [o][t*256+c]
__device__ __half g_wl[OO*KK];                // weight lo fp16
__device__ float g_spwt[2*9*256];             // sp weights transposed [ch][tap][c]

// ================= helpers (plain sm_80+ PTX only) =================
__device__ __forceinline__ uint32_t s2u(const void* p) {
    uint32_t a;
    asm("{ .reg .u64 t; cvta.to.shared.u64 t, %1; cvt.u32.u64 %0, t; }" : "=r"(a) : "l"(p));
    return a;
}
// pack two fp32 -> fp16x2 (first arg -> low half)
__device__ __forceinline__ uint32_t hpack(float lo, float hi) {
    uint32_t r;
    asm("cvt.rn.f16x2.f32 %0, %1, %2;" : "=r"(r) : "f"(hi), "f"(lo));
    return r;
}
__device__ __forceinline__ void sts64(uint32_t a, uint32_t x, uint32_t y) {
    asm volatile("st.shared.v2.b32 [%0], {%1, %2};" :: "r"(a), "r"(x), "r"(y) : "memory");
}
__device__ __forceinline__ void ldm4(uint32_t* r, uint32_t a) {
    asm volatile("ldmatrix.sync.aligned.m8n8.x4.shared.b16 {%0,%1,%2,%3}, [%4];"
                 : "=r"(r[0]), "=r"(r[1]), "=r"(r[2]), "=r"(r[3]) : "r"(a));
}
__device__ __forceinline__ void mma16816(float* d, const uint32_t* a, uint32_t b0, uint32_t b1) {
    asm volatile("mma.sync.aligned.m16n8k16.row.col.f32.f16.f16.f32 "
                 "{%0,%1,%2,%3}, {%4,%5,%6,%7}, {%8,%9}, {%0,%1,%2,%3};"
                 : "+f"(d[0]), "+f"(d[1]), "+f"(d[2]), "+f"(d[3])
                 : "r"(a[0]), "r"(a[1]), "r"(a[2]), "r"(a[3]), "r"(b0), "r"(b1));
}
__device__ __forceinline__ void cpasync16(uint32_t dst, const void* src) {
    asm volatile("cp.async.cg.shared.global [%0], [%1], 16;"
                 :: "r"(dst), "l"(__cvta_generic_to_global(src)) : "memory");
}

// smem layout (bytes)
#define OFF_A   0            // 64 x 72 fp16 = 9216
#define OFF_CRD 9216         // 8 arrays x 64 x 4B = 2048
#define OFF_BHI 11264        // 256 x 128B swizzled
#define OFF_BLO 44032
#define SMEM_DYN 76800

// ============ K1: NCHW -> NHWC transpose ============
__global__ void k_transpose(const float* __restrict__ x) {
    __shared__ float tile[32][33];
    int hw0 = blockIdx.x * 32, c0 = blockIdx.y * 32, b = blockIdx.z;
    int tx = threadIdx.x, ty = threadIdx.y;
#pragma unroll
    for (int i = 0; i < 4; ++i)
        tile[ty + i*8][tx] = x[(b*CC + c0 + ty + i*8)*HWP + hw0 + tx];
    __syncthreads();
#pragma unroll
    for (int i = 0; i < 4; ++i)
        g_xn[((size_t)b*HWP + hw0 + ty + i*8)*CC + c0 + tx] = tile[tx][ty + i*8];
}

// ============ K2: weight split to fp16 hi/lo, [o][t*256+c] ============
__global__ void k_wsplit(const float* __restrict__ w) {
    int idx = blockIdx.x*256 + threadIdx.x;      // o*KK + t*256 + c
    int o = idx / KK, k = idx - o*KK;
    int t = k >> 8, c = k & 255;
    float v = w[(o*CC + c)*9 + t];
    __half h = __float2half_rn(v);
    g_wh[idx] = h;
    g_wl[idx] = __float2half_rn(v - __half2float(h));
}

// ============ K2b: sp weight transpose [ch][tap][c] ============
__global__ void k_spwt(const float* __restrict__ spw) {
    int i = blockIdx.x*256 + threadIdx.x;        // ch*2304 + t*256 + c
    if (i >= 2*9*256) return;
    int ch = i / 2304, rem = i - ch*2304;
    int t = rem >> 8, c = rem & 255;
    g_spwt[i] = spw[(ch*CC + c)*9 + t];
}

// ============ K3: scale-predictor conv, warp-per-pixel on NHWC ============
__global__ __launch_bounds__(256)
void k_spconv(const float* __restrict__ spb) {
    int tid = threadIdx.x;
    int warp = tid >> 5, lane = tid & 31;
    int p = blockIdx.x*8 + warp;
    int b = p / HWP, r = p - b*HWP;
    int y = r / WW, x = r - y*WW;
    float a0 = 0.f, a1 = 0.f;
#pragma unroll
    for (int t = 0; t < 9; ++t) {
        int dy = t/3 - 1, dx = t%3 - 1;
        int yy = y + dy, xx = x + dx;
        if (yy < 0 || yy >= HH || xx < 0 || xx >= WW) continue;
        const float* xr = g_xn + ((size_t)b*HWP + yy*WW + xx)*CC;
        const float* w0 = g_spwt + t*256;
        const float* w1 = g_spwt + 2304 + t*256;
#pragma unroll
        for (int ci = 0; ci < 2; ++ci) {
            int c = lane*4 + ci*128;
            float4 xv = *(const float4*)(xr + c);
            float4 wa = *(const float4*)(w0 + c);
            float4 wb = *(const float4*)(w1 + c);
            a0 += xv.x*wa.x + xv.y*wa.y + xv.z*wa.z + xv.w*wa.w;
            a1 += xv.x*wb.x + xv.y*wb.y + xv.z*wb.z + xv.w*wb.w;
        }
    }
#pragma unroll
    for (int off = 16; off; off >>= 1) {
        a0 += __shfl_down_sync(0xffffffffu, a0, off);
        a1 += __shfl_down_sync(0xffffffffu, a1, off);
    }
    if (lane == 0) {
        g_sx[p] = expf(fminf(fmaxf(a0 + spb[0], -2.f), 2.f));
        g_sy[p] = expf(fminf(fmaxf(a1 + spb[1], -2.f), 2.f));
    }
}

// ============ K4: main — gather + fp16 2-term HMMA, 2 CTAs/SM ============
// 256 threads = 8 warps (2M x 4N). CTA tile M=64 px, N=256 out.
__global__ void __launch_bounds__(256, 2)
k_main(const float* __restrict__ bias, float* __restrict__ out) {
    extern __shared__ char sm[];
    const uint32_t SMB = s2u(sm);
    const uint32_t AT  = SMB + OFF_A;
    const uint32_t BHI = SMB + OFF_BHI, BLO = SMB + OFF_BLO;
    int*   so00 = (int*)  (sm + OFF_CRD);
    int*   so01 = (int*)  (sm + OFF_CRD + 256);
    int*   so10 = (int*)  (sm + OFF_CRD + 512);
    int*   so11 = (int*)  (sm + OFF_CRD + 768);
    float* sw00 = (float*)(sm + OFF_CRD + 1024);
    float* sw01 = (float*)(sm + OFF_CRD + 1280);
    float* sw10 = (float*)(sm + OFF_CRD + 1536);
    float* sw11 = (float*)(sm + OFF_CRD + 1792);

    const int tid  = threadIdx.x;
    const int wid  = tid >> 5, lane = tid & 31;
    const int wm   = wid & 1;          // M group (32 rows)
    const int wn   = wid >> 1;         // N group (64 cols)
    const int m0 = blockIdx.x * MT;
    const int b  = m0 / HWP;
    const int pb = b * HWP;
    const int p0 = m0 - pb;
    // anti-phase skew between the 2 co-resident CTAs (bid vs bid+148: bit2 flips)
    const int phase = ((blockIdx.x >> 2) & 1) * 16;

    // ldmatrix lane addressing
    const int lrow = lane & 7;
    const int a_row16 = lrow + ((lane >> 3) & 1) * 8;
    const int a_k8    = (lane >> 4) * 8;
    const uint32_t aoff0 = (uint32_t)((wm*32 + a_row16) * SA + a_k8) * 2;
    const uint32_t aoff1 = aoff0 + 16*SA*2;
    const int b_n   = (lane >> 4) * 8 + lrow;
    const int brow  = wn*64 + b_n;
    const uint32_t bbase = (uint32_t)brow * 128u;
    const uint32_t bxor  = ((uint32_t)brow & 7u) << 4;
    const uint32_t bkk   = ((lane >> 3) & 1) * 16;

    float acc[2][8][4];
#pragma unroll
    for (int i = 0; i < 2; ++i)
#pragma unroll
        for (int j = 0; j < 8; ++j)
#pragma unroll
            for (int q = 0; q < 4; ++q) acc[i][j][q] = 0.f;

    for (int ic = 0; ic < NCHUNK; ++ic) {
        const int kc = (ic + phase) % NCHUNK;
        const int t = kc >> 2;
        const int cbase = (kc & 3) * 64;

        __syncthreads();   // prev MMA done: A/B/coords smem free

        // ---- B tiles via cp.async into swizzled layout (overlaps A gather) ----
#pragma unroll
        for (int it = 0; it < 16; ++it) {
            int tau = tid + it*256;
            int tl = tau >> 11;
            int r  = (tau >> 3) & 255;
            int u  = tau & 7;
            const __half* src = (tl ? g_wl : g_wh) + (size_t)r*KK + kc*KC + u*8;
            uint32_t off = (uint32_t)(r*128 + u*16);
            uint32_t dst = (tl ? BLO : BHI) + (off ^ ((off >> 3) & 0x70u));
            cpasync16(dst, src);
        }
        asm volatile("cp.async.commit_group;" ::: "memory");

        if ((kc & 3) == 0) {     // new tap: bilinear coords (1 px/thread, tid<64)
            if (tid < MT) {
                int p = m0 + tid;
                int r = p - pb;
                int y = r / WW, xx = r - y*WW;
                float cx = (float)(t % 3 - 1), cy = (float)(t / 3 - 1);
                float gx = fminf(fmaxf((float)xx + cx*g_sx[p], 0.f), (float)(WW-1));
                float gy = fminf(fmaxf((float)y  + cy*g_sy[p], 0.f), (float)(HH-1));
                float x0f = floorf(gx), y0f = floorf(gy);
                float wx = gx - x0f, wy = gy - y0f;
                int ix0 = (int)x0f, iy0 = (int)y0f;
                int ix1 = min(ix0+1, WW-1), iy1 = min(iy0+1, HH-1);
                int r0 = pb + iy0*WW, r1 = pb + iy1*WW;
                so00[tid] = (r0 + ix0) * CC;
                so01[tid] = (r0 + ix1) * CC;
                so10[tid] = (r1 + ix0) * CC;
                so11[tid] = (r1 + ix1) * CC;
                sw00[tid] = (1.f-wx)*(1.f-wy);
                sw01[tid] = wx*(1.f-wy);
                sw10[tid] = (1.f-wx)*wy;
                sw11[tid] = wx*wy;
            }
            __syncthreads();
        }

        // ---- A gather: 64 px x 64 k -> fp16 padded tile ----
#pragma unroll
        for (int it = 0; it < 4; ++it) {
            int tau = tid + it*256;
            int p = tau >> 4;          // 0..63
            int j = tau & 15;          // 4-channel group
            int cb = cbase + j*4;
            const float4 v00 = *(const float4*)(g_xn + (size_t)so00[p] + cb);
            const float4 v01 = *(const float4*)(g_xn + (size_t)so01[p] + cb);
            const float4 v10 = *(const float4*)(g_xn + (size_t)so10[p] + cb);
            const float4 v11 = *(const float4*)(g_xn + (size_t)so11[p] + cb);
            float w00 = sw00[p], w01 = sw01[p], w10 = sw10[p], w11 = sw11[p];
            float f0 = w00*v00.x + w01*v01.x + w10*v10.x + w11*v11.x;
            float f1 = w00*v00.y + w01*v01.y + w10*v10.y + w11*v11.y;
            float f2 = w00*v00.z + w01*v01.z + w10*v10.z + w11*v11.z;
            float f3 = w00*v00.w + w01*v01.w + w10*v10.w + w11*v11.w;
            uint32_t h0 = hpack(f0, f1);
            uint32_t h1 = hpack(f2, f3);
            sts64(AT + (uint32_t)(p*SA*2 + j*8), h0, h1);
        }
        asm volatile("cp.async.wait_group 0;" ::: "memory");
        __syncthreads();

        // ---- MMA: 4 k16 steps x 2 terms ----
#pragma unroll
        for (int ks = 0; ks < 4; ++ks) {
            uint32_t a0[4], a1[4];
            ldm4(a0, AT + aoff0 + ks*32);
            ldm4(a1, AT + aoff1 + ks*32);
            uint32_t koff = ((uint32_t)(ks*32) + bkk) ^ bxor;
#pragma unroll
            for (int nt = 0; nt < 4; ++nt) {
                uint32_t bh[4], bl[4];
                ldm4(bh, BHI + bbase + nt*(16*128) + koff);
                ldm4(bl, BLO + bbase + nt*(16*128) + koff);
                int n0 = nt*2;
                mma16816(acc[0][n0],   a0, bh[0], bh[1]);
                mma16816(acc[0][n0+1], a0, bh[2], bh[3]);
                mma16816(acc[1][n0],   a1, bh[0], bh[1]);
                mma16816(acc[1][n0+1], a1, bh[2], bh[3]);
                mma16816(acc[0][n0],   a0, bl[0], bl[1]);
                mma16816(acc[0][n0+1], a0, bl[2], bl[3]);
                mma16816(acc[1][n0],   a1, bl[0], bl[1]);
                mma16816(acc[1][n0+1], a1, bl[2], bl[3]);
            }
        }
    }

    // ---- epilogue: stage all 256 o x 64 px through smem (stride 68) ----
    __syncthreads();
    float* ep = (float*)sm;
    const int qrow = lane >> 2;
    const int qcol = (lane & 3) * 2;
#pragma unroll
    for (int mt = 0; mt < 2; ++mt) {
#pragma unroll
        for (int nn = 0; nn < 8; ++nn) {
            int ol = wn*64 + nn*8 + qcol;
            int pr = wm*32 + mt*16 + qrow;
            ep[ol*68 + pr]         = acc[mt][nn][0];
            ep[(ol+1)*68 + pr]     = acc[mt][nn][1];
            ep[ol*68 + pr + 8]     = acc[mt][nn][2];
            ep[(ol+1)*68 + pr + 8] = acc[mt][nn][3];
        }
    }
    __syncthreads();
#pragma unroll
    for (int i = 0; i < 16; ++i) {
        int o = i*16 + (tid >> 4);
        int q = tid & 15;
        float bv = __ldg(&bias[o]);
        const float* er = ep + o*68 + q*4;
        float4 v = make_float4(er[0]+bv, er[1]+bv, er[2]+bv, er[3]+bv);
        *(float4*)(out + ((size_t)(b*OO + o))*HWP + p0 + q*4) = v;
    }
}

extern "C" void kernel_launch(void* const* d_in, const int* in_sizes, int n_in,
                              void* d_out, int out_size) {
    const float* x    = (const float*)d_in[0];
    const float* w    = (const float*)d_in[1];
    const float* bias = (const float*)d_in[2];
    const float* spw  = (const float*)d_in[3];
    const float* spb  = (const float*)d_in[4];
    float* out = (float*)d_out;

    cudaFuncSetAttribute(k_main, cudaFuncAttributeMaxDynamicSharedMemorySize, SMEM_DYN);

    k_transpose<<<dim3(HWP/32, CC/32, BB), dim3(32, 8)>>>(x);
    k_wsplit  <<<(OO*KK)/256, 256>>>(w);
    k_spwt    <<<(2*9*256 + 255)/256, 256>>>(spw);
    k_spconv  <<<(BB*HWP)/8, 256>>>(spb);
    k_main    <<<(BB*HWP)/MT, 256, SMEM_DYN>>>(bias, out);
}